// round 7
// baseline (speedup 1.0000x reference)
#include <cuda_runtime.h>
#include <cuda_fp16.h>
#include <cstdint>

// LightGCN propagation: N=100000, E=1600000, D=64, L=3.
// out = (x0 + x1 + x2 + x3)/4, x_{l+1} = A_norm @ x_l (with self loops).
//
// R7: the layer loop was gather-LATENCY bound (in-order issue serialized the
// per-edge LDG chain, MLP~1). Batch 8 edges per inner step: 16 shfls, then 8
// back-to-back gather LDGs (MLP=8), then 16 FMAs. fp16 rows kept (128B/row).

#define NN 100000
#define EE 1600000
#define DD 64
#define ND (NN * DD)       // 6,400,000 floats
#define ND4 (ND / 4)       // 1,600,000
#define ND2 (ND / 2)       // 3,200,000 half2
#define NB 391             // ceil(NN / 256)

// Scratch (allocation-free: __device__ globals)
__device__ int g_is32;
__device__ float g_deg[NN];      // source-occurrence degree (incl. self loop)
__device__ float g_dinv[NN];
__device__ int g_indeg[NN];      // destination in-degree (excl. self loop)
__device__ int g_part[NB];
__device__ int g_boff[NB];
__device__ int g_start[NN + 1];  // CSR row starts (by destination)
__device__ int g_cursor[NN];
__device__ uint2 g_csr[EE];      // packed (src, norm_bits), grouped by dst
__device__ __half2 g_h0[ND2];    // x0 (emb) in half
__device__ __half2 g_h1[ND2];    // x1
__device__ __half2 g_h2[ND2];    // x2

// ---------------------------------------------------------------------------
// Init: degrees + index-dtype detection (JAX w/o x64 demotes int64 -> int32;
// element count is identical either way, so sample values to disambiguate).
// ---------------------------------------------------------------------------
__global__ __launch_bounds__(256) void k_init(const void* __restrict__ idx) {
    int i = blockIdx.x * blockDim.x + threadIdx.x;
    if (i < NN) {
        g_deg[i] = 1.0f;   // self loop contributes 1 to every degree
        g_indeg[i] = 0;
    }
    if (i == 0) {
        const long long* p = (const long long*)idx;
        int is64 = 1;
        for (int k = 0; k < 256; k++) {
            long long v = p[k];
            if (v < 0 || v >= (long long)NN) { is64 = 0; break; }
        }
        g_is32 = !is64;
    }
}

// Convert emb (fp32) -> g_h0 (half), float4 -> 2x half2 per thread.
__global__ __launch_bounds__(256) void k_h0(const float4* __restrict__ emb4) {
    int i = blockIdx.x * blockDim.x + threadIdx.x;
    if (i >= ND4) return;
    float4 v = __ldg(&emb4[i]);
    __half2 a = __floats2half2_rn(v.x, v.y);
    __half2 b = __floats2half2_rn(v.z, v.w);
    uint2 p;
    p.x = *reinterpret_cast<unsigned*>(&a);
    p.y = *reinterpret_cast<unsigned*>(&b);
    reinterpret_cast<uint2*>(g_h0)[i] = p;
}

// 4 edges per thread, vectorized int4 loads on the int32 path.
__global__ __launch_bounds__(256) void k_count(const void* __restrict__ idx) {
    int t = blockIdx.x * blockDim.x + threadIdx.x;
    int e = t * 4;
    if (e >= EE) return;
    int s0, s1, s2, s3, d0, d1, d2, d3;
    if (g_is32) {
        const int4* p = (const int4*)idx;
        int4 s = __ldg(&p[t]);
        int4 d = __ldg(&p[EE / 4 + t]);
        s0 = s.x; s1 = s.y; s2 = s.z; s3 = s.w;
        d0 = d.x; d1 = d.y; d2 = d.z; d3 = d.w;
    } else {
        const long long* p = (const long long*)idx;
        s0 = (int)p[e];      s1 = (int)p[e + 1];
        s2 = (int)p[e + 2];  s3 = (int)p[e + 3];
        d0 = (int)p[EE + e];     d1 = (int)p[EE + e + 1];
        d2 = (int)p[EE + e + 2]; d3 = (int)p[EE + e + 3];
    }
    atomicAdd(&g_deg[s0], 1.0f); atomicAdd(&g_deg[s1], 1.0f);
    atomicAdd(&g_deg[s2], 1.0f); atomicAdd(&g_deg[s3], 1.0f);
    atomicAdd(&g_indeg[d0], 1);  atomicAdd(&g_indeg[d1], 1);
    atomicAdd(&g_indeg[d2], 1);  atomicAdd(&g_indeg[d3], 1);
}

// ---------------------------------------------------------------------------
// Scan of in-degrees -> CSR starts (3-kernel hierarchy). scan1 also computes
// dinv (both depend only on k_count).
// ---------------------------------------------------------------------------
__global__ __launch_bounds__(256) void k_scan1() {
    __shared__ int sh[256];
    int i = blockIdx.x * 256 + threadIdx.x;
    sh[threadIdx.x] = (i < NN) ? g_indeg[i] : 0;
    if (i < NN) {
        float d = g_deg[i];
        g_dinv[i] = (d > 0.0f) ? rsqrtf(d) : 0.0f;
    }
    __syncthreads();
    for (int s = 128; s > 0; s >>= 1) {
        if (threadIdx.x < s) sh[threadIdx.x] += sh[threadIdx.x + s];
        __syncthreads();
    }
    if (threadIdx.x == 0) g_part[blockIdx.x] = sh[0];
}

__global__ __launch_bounds__(512) void k_scan2() {
    __shared__ int sh[512];
    int t = threadIdx.x;
    sh[t] = (t < NB) ? g_part[t] : 0;
    __syncthreads();
    for (int off = 1; off < 512; off <<= 1) {
        int v = (t >= off) ? sh[t - off] : 0;
        __syncthreads();
        sh[t] += v;
        __syncthreads();
    }
    if (t < NB) g_boff[t] = (t == 0) ? 0 : sh[t - 1];
}

__global__ __launch_bounds__(256) void k_scan3() {
    __shared__ int sh[256];
    int i = blockIdx.x * 256 + threadIdx.x;
    int v = (i < NN) ? g_indeg[i] : 0;
    sh[threadIdx.x] = v;
    __syncthreads();
    for (int off = 1; off < 256; off <<= 1) {
        int t = (threadIdx.x >= off) ? sh[threadIdx.x - off] : 0;
        __syncthreads();
        sh[threadIdx.x] += t;
        __syncthreads();
    }
    if (i < NN) {
        int excl = g_boff[blockIdx.x] + sh[threadIdx.x] - v;
        g_start[i] = excl;
        g_cursor[i] = excl;
        if (i == NN - 1) g_start[NN] = excl + v;
    }
}

// Fill CSR: 2 edges per thread, vectorized loads on the int32 path.
__global__ __launch_bounds__(256) void k_fill(const void* __restrict__ idx,
                                              const float* __restrict__ w) {
    int t = blockIdx.x * blockDim.x + threadIdx.x;
    int e = t * 2;
    if (e >= EE) return;
    int s0, s1, d0, d1;
    if (g_is32) {
        const int2* p = (const int2*)idx;
        int2 s = __ldg(&p[t]);
        int2 d = __ldg(&p[EE / 2 + t]);
        s0 = s.x; s1 = s.y; d0 = d.x; d1 = d.y;
    } else {
        const long long* p = (const long long*)idx;
        s0 = (int)p[e]; s1 = (int)p[e + 1];
        d0 = (int)p[EE + e]; d1 = (int)p[EE + e + 1];
    }
    float2 wv = __ldg((const float2*)(w + e));
    float n0 = g_dinv[s0] * wv.x * g_dinv[d0];
    float n1 = g_dinv[s1] * wv.y * g_dinv[d1];
    int p0 = atomicAdd(&g_cursor[d0], 1);
    g_csr[p0] = make_uint2((unsigned)s0, __float_as_uint(n0));
    int p1 = atomicAdd(&g_cursor[d1], 1);
    g_csr[p1] = make_uint2((unsigned)s1, __float_as_uint(n1));
}

// ---------------------------------------------------------------------------
// Layer kernel: ONE WARP per node; lane owns one half2 (2 feature columns).
// Edge records loaded coalesced (32/warp), broadcast via shfl. 8-edge batches:
// all shfls, then 8 back-to-back gather LDGs (MLP=8), then FMAs. fp32 accum.
//   acc = dinv[n]^2 * xOld[n] + sum_{e in CSR[n]} norm[e] * xOld[src[e]]
// mode 0/1: xNew = half(acc)
// mode 2:   out = (emb + x1 + xOld + acc) * 0.25  in fp32 (xOld == x2)
// ---------------------------------------------------------------------------
__global__ __launch_bounds__(256) void k_layer(const __half2* __restrict__ xOld,
                                               __half2* __restrict__ xNew,
                                               const float2* __restrict__ emb2,
                                               const __half2* __restrict__ x1h,
                                               float2* __restrict__ out2,
                                               int mode) {
    int lane = threadIdx.x & 31;
    int node = blockIdx.x * 8 + (threadIdx.x >> 5);  // grid covers exactly NN

    int start = g_start[node];
    int end = g_start[node + 1];
    float s = g_dinv[node];
    s *= s;

    int o = node * 32 + lane;
    float2 v0 = __half22float2(xOld[o]);
    float ax = s * v0.x, ay = s * v0.y;

    for (int base = start; base < end; base += 32) {
        int e = base + lane;
        uint2 ed = (e < end) ? __ldg(&g_csr[e]) : make_uint2(0u, 0u);
        int m = end - base;
        if (m > 32) m = 32;
        int j = 0;
        for (; j + 8 <= m; j += 8) {
            unsigned sj[8];
            float nj[8];
            __half2 vj[8];
            #pragma unroll
            for (int k = 0; k < 8; k++) {
                sj[k] = __shfl_sync(0xFFFFFFFFu, ed.x, j + k);
                nj[k] = __uint_as_float(__shfl_sync(0xFFFFFFFFu, ed.y, j + k));
            }
            #pragma unroll
            for (int k = 0; k < 8; k++) {
                vj[k] = __ldg(&xOld[sj[k] * 32 + lane]);
            }
            #pragma unroll
            for (int k = 0; k < 8; k++) {
                float2 v = __half22float2(vj[k]);
                ax = fmaf(nj[k], v.x, ax);
                ay = fmaf(nj[k], v.y, ay);
            }
        }
        if (j + 4 <= m) {
            unsigned sj[4];
            float nj[4];
            __half2 vj[4];
            #pragma unroll
            for (int k = 0; k < 4; k++) {
                sj[k] = __shfl_sync(0xFFFFFFFFu, ed.x, j + k);
                nj[k] = __uint_as_float(__shfl_sync(0xFFFFFFFFu, ed.y, j + k));
            }
            #pragma unroll
            for (int k = 0; k < 4; k++) {
                vj[k] = __ldg(&xOld[sj[k] * 32 + lane]);
            }
            #pragma unroll
            for (int k = 0; k < 4; k++) {
                float2 v = __half22float2(vj[k]);
                ax = fmaf(nj[k], v.x, ax);
                ay = fmaf(nj[k], v.y, ay);
            }
            j += 4;
        }
        for (; j < m; j++) {
            unsigned sj = __shfl_sync(0xFFFFFFFFu, ed.x, j);
            float nf = __uint_as_float(__shfl_sync(0xFFFFFFFFu, ed.y, j));
            float2 v = __half22float2(__ldg(&xOld[sj * 32 + lane]));
            ax = fmaf(nf, v.x, ax);
            ay = fmaf(nf, v.y, ay);
        }
    }

    if (mode != 2) {
        xNew[o] = __floats2half2_rn(ax, ay);
    } else {
        float2 a = __ldg(&emb2[o]);
        float2 b = __half22float2(__ldg(&x1h[o]));
        out2[o] = make_float2((a.x + b.x + v0.x + ax) * 0.25f,
                              (a.y + b.y + v0.y + ay) * 0.25f);
    }
}

// ---------------------------------------------------------------------------
extern "C" void kernel_launch(void* const* d_in, const int* in_sizes, int n_in,
                              void* d_out, int out_size) {
    // Bind inputs by unique element count (robust to metadata ordering).
    const float* emb = nullptr;   // 6,400,000 f32
    const float* ew = nullptr;    // 1,600,000 f32
    const void* idx = nullptr;    // 3,200,000 elems (int32 or int64, detected)
    for (int i = 0; i < n_in; i++) {
        if (in_sizes[i] == ND) emb = (const float*)d_in[i];
        else if (in_sizes[i] == EE) ew = (const float*)d_in[i];
        else if (in_sizes[i] == 2 * EE) idx = d_in[i];
    }
    if (!emb) emb = (const float*)d_in[0];
    if (!ew) ew = (const float*)d_in[1];
    if (!idx) idx = d_in[2];

    float2* out2 = (float2*)d_out;

    __half2* h0;
    __half2* h1;
    __half2* h2;
    cudaGetSymbolAddress((void**)&h0, g_h0);
    cudaGetSymbolAddress((void**)&h1, g_h1);
    cudaGetSymbolAddress((void**)&h2, g_h2);

    const int T = 256;
    const int gN = (NN + T - 1) / T;            // 391
    const int gE4 = (EE / 4 + T - 1) / T;       // 1563
    const int gE2 = (EE / 2 + T - 1) / T;       // 3125
    const int gC = (ND4 + T - 1) / T;           // 6250
    const int gL = NN / 8;                      // 12500 (exact, 8 warps/block)

    // Precompute: degrees, dinv, CSR, half copy of emb
    k_init<<<gN, T>>>(idx);
    k_count<<<gE4, T>>>(idx);
    k_h0<<<gC, T>>>((const float4*)emb);
    k_scan1<<<NB, T>>>();   // also computes dinv
    k_scan2<<<1, 512>>>();
    k_scan3<<<NB, T>>>();
    k_fill<<<gE2, T>>>(idx, ew);

    // Layer 1: x1 <- A @ x0
    k_layer<<<gL, T>>>(h0, h1, nullptr, nullptr, nullptr, 0);
    // Layer 2: x2 <- A @ x1
    k_layer<<<gL, T>>>(h1, h2, nullptr, nullptr, nullptr, 1);
    // Layer 3: out = (x0 + x1 + x2 + A @ x2) / 4   (fp32 out)
    k_layer<<<gL, T>>>(h2, nullptr, (const float2*)emb, h1, out2, 2);
}

// round 8
// speedup vs baseline: 1.1104x; 1.1104x over previous
#include <cuda_runtime.h>
#include <cuda_fp16.h>
#include <cstdint>

// LightGCN propagation: N=100000, E=1600000, D=64, L=3.
// out = (x0 + x1 + x2 + x3)/4, x_{l+1} = A_norm @ x_l (with self loops).
//
// R8: layer loop is SHFL/MIO-issue bound. 16-lane groups (2 nodes per warp)
// share each width-16 shfl broadcast between both groups (shfl/edge = 1), with
// warp-uniform trip counts (no divergence). fp16 rows kept. Scan collapsed to
// one kernel (atomic block-base; layer reads start+indeg, so CSR bucket order
// need not be monotonic). 7 launches total.

#define NN 100000
#define EE 1600000
#define DD 64
#define ND (NN * DD)       // 6,400,000 floats
#define ND4 (ND / 4)       // 1,600,000
#define NB 391             // ceil(NN / 256)

// Scratch (allocation-free: __device__ globals)
__device__ int g_is32;
__device__ int g_base;           // atomic cursor for scan block bases
__device__ float g_deg[NN];      // source-occurrence degree (incl. self loop)
__device__ float g_dinv[NN];
__device__ int g_indeg[NN];      // destination in-degree (excl. self loop)
__device__ int g_start[NN];      // CSR bucket start (by destination)
__device__ int g_cursor[NN];
__device__ uint2 g_csr[EE];      // packed (src, norm_bits), grouped by dst
__device__ uint2 g_h0[ND4];      // x0 (emb) as 2x half2 per uint2
__device__ uint2 g_h1[ND4];      // x1
__device__ uint2 g_h2[ND4];      // x2

// ---------------------------------------------------------------------------
// Init: zero degrees, detect index dtype (JAX w/o x64 demotes int64 -> int32;
// element counts are identical, so sample values), convert emb -> fp16.
// Grid covers ND4 (h0 convert); first NN threads also init degree arrays.
// ---------------------------------------------------------------------------
__global__ __launch_bounds__(256) void k_init(const void* __restrict__ idx,
                                              const float4* __restrict__ emb4) {
    int i = blockIdx.x * blockDim.x + threadIdx.x;
    if (i < NN) {
        g_deg[i] = 1.0f;   // self loop contributes 1 to every degree
        g_indeg[i] = 0;
    }
    if (i == 0) {
        g_base = 0;
        const long long* p = (const long long*)idx;
        int is64 = 1;
        for (int k = 0; k < 256; k++) {
            long long v = p[k];
            if (v < 0 || v >= (long long)NN) { is64 = 0; break; }
        }
        g_is32 = !is64;
    }
    if (i < ND4) {
        float4 v = __ldg(&emb4[i]);
        __half2 a = __floats2half2_rn(v.x, v.y);
        __half2 b = __floats2half2_rn(v.z, v.w);
        uint2 pck;
        pck.x = *reinterpret_cast<unsigned*>(&a);
        pck.y = *reinterpret_cast<unsigned*>(&b);
        g_h0[i] = pck;
    }
}

// 4 edges per thread, vectorized int4 loads on the int32 path.
__global__ __launch_bounds__(256) void k_count(const void* __restrict__ idx) {
    int t = blockIdx.x * blockDim.x + threadIdx.x;
    int e = t * 4;
    if (e >= EE) return;
    int s0, s1, s2, s3, d0, d1, d2, d3;
    if (g_is32) {
        const int4* p = (const int4*)idx;
        int4 s = __ldg(&p[t]);
        int4 d = __ldg(&p[EE / 4 + t]);
        s0 = s.x; s1 = s.y; s2 = s.z; s3 = s.w;
        d0 = d.x; d1 = d.y; d2 = d.z; d3 = d.w;
    } else {
        const long long* p = (const long long*)idx;
        s0 = (int)p[e];      s1 = (int)p[e + 1];
        s2 = (int)p[e + 2];  s3 = (int)p[e + 3];
        d0 = (int)p[EE + e];     d1 = (int)p[EE + e + 1];
        d2 = (int)p[EE + e + 2]; d3 = (int)p[EE + e + 3];
    }
    atomicAdd(&g_deg[s0], 1.0f); atomicAdd(&g_deg[s1], 1.0f);
    atomicAdd(&g_deg[s2], 1.0f); atomicAdd(&g_deg[s3], 1.0f);
    atomicAdd(&g_indeg[d0], 1);  atomicAdd(&g_indeg[d1], 1);
    atomicAdd(&g_indeg[d2], 1);  atomicAdd(&g_indeg[d3], 1);
}

// ---------------------------------------------------------------------------
// Single-kernel "scan": intra-block inclusive prefix of indeg; block base via
// atomic reservation (bucket order across blocks is arbitrary — the layer
// kernel uses start+indeg, never start[node+1]). Also computes dinv.
// ---------------------------------------------------------------------------
__global__ __launch_bounds__(256) void k_scan() {
    __shared__ int sh[256];
    __shared__ int sbase;
    int i = blockIdx.x * 256 + threadIdx.x;
    int v = (i < NN) ? g_indeg[i] : 0;
    if (i < NN) {
        float d = g_deg[i];
        g_dinv[i] = (d > 0.0f) ? rsqrtf(d) : 0.0f;
    }
    sh[threadIdx.x] = v;
    __syncthreads();
    for (int off = 1; off < 256; off <<= 1) {
        int t = (threadIdx.x >= off) ? sh[threadIdx.x - off] : 0;
        __syncthreads();
        sh[threadIdx.x] += t;
        __syncthreads();
    }
    if (threadIdx.x == 255) sbase = atomicAdd(&g_base, sh[255]);
    __syncthreads();
    if (i < NN) {
        int excl = sbase + sh[threadIdx.x] - v;
        g_start[i] = excl;
        g_cursor[i] = excl;
    }
}

// Fill CSR: 2 edges per thread, vectorized loads on the int32 path.
__global__ __launch_bounds__(256) void k_fill(const void* __restrict__ idx,
                                              const float* __restrict__ w) {
    int t = blockIdx.x * blockDim.x + threadIdx.x;
    int e = t * 2;
    if (e >= EE) return;
    int s0, s1, d0, d1;
    if (g_is32) {
        const int2* p = (const int2*)idx;
        int2 s = __ldg(&p[t]);
        int2 d = __ldg(&p[EE / 2 + t]);
        s0 = s.x; s1 = s.y; d0 = d.x; d1 = d.y;
    } else {
        const long long* p = (const long long*)idx;
        s0 = (int)p[e]; s1 = (int)p[e + 1];
        d0 = (int)p[EE + e]; d1 = (int)p[EE + e + 1];
    }
    float2 wv = __ldg((const float2*)(w + e));
    float n0 = g_dinv[s0] * wv.x * g_dinv[d0];
    float n1 = g_dinv[s1] * wv.y * g_dinv[d1];
    int p0 = atomicAdd(&g_cursor[d0], 1);
    g_csr[p0] = make_uint2((unsigned)s0, __float_as_uint(n0));
    int p1 = atomicAdd(&g_cursor[d1], 1);
    g_csr[p1] = make_uint2((unsigned)s1, __float_as_uint(n1));
}

// ---------------------------------------------------------------------------
// Layer kernel: 16-lane group per node (2 nodes/warp). Lane owns uint2 =
// 2x half2 = 4 features. Each width-16 SHFL serves BOTH groups -> 1 shfl-pair
// per edge (the MIO bottleneck). Warp-uniform trip count maxm = max over the
// 2 groups; padded iterations use norm=0 and gather row 0 (L1-hot). fp32 accum.
//   acc = dinv[n]^2 * xOld[n] + sum_{e in CSR[n]} norm[e] * xOld[src[e]]
// mode 0/1: xNew = half(acc)
// mode 2:   out = (emb + x1 + xOld + acc) * 0.25 in fp32 (xOld == x2)
// ---------------------------------------------------------------------------
__global__ __launch_bounds__(256) void k_layer(const uint2* __restrict__ xOld,
                                               uint2* __restrict__ xNew,
                                               const float2* __restrict__ emb2,
                                               const uint2* __restrict__ x1h,
                                               float2* __restrict__ out2,
                                               int mode) {
    int glane = threadIdx.x & 15;
    int node = blockIdx.x * 16 + (threadIdx.x >> 4);  // grid covers exactly NN

    int start = g_start[node];
    int m = g_indeg[node];
    float s = g_dinv[node];
    s *= s;

    int o = node * 16 + glane;
    uint2 r0 = xOld[o];
    float2 va = __half22float2(*reinterpret_cast<__half2*>(&r0.x));
    float2 vb = __half22float2(*reinterpret_cast<__half2*>(&r0.y));
    float a0 = s * va.x, a1 = s * va.y, a2 = s * vb.x, a3 = s * vb.y;

    // Warp-uniform iteration bound across the 2 groups in this warp.
    int mo = __shfl_xor_sync(0xFFFFFFFFu, m, 16);
    int maxm = m > mo ? m : mo;

    for (int base = 0; base < maxm; base += 16) {
        uint2 ed = make_uint2(0u, 0u);
        if (base + glane < m) ed = __ldg(&g_csr[start + base + glane]);
        int t = maxm - base;
        if (t > 16) t = 16;
        for (int j = 0; j < t; j++) {
            unsigned sj = __shfl_sync(0xFFFFFFFFu, ed.x, j, 16);
            float nf = __uint_as_float(__shfl_sync(0xFFFFFFFFu, ed.y, j, 16));
            uint2 vr = __ldg(&xOld[sj * 16 + glane]);
            float2 pa = __half22float2(*reinterpret_cast<__half2*>(&vr.x));
            float2 pb = __half22float2(*reinterpret_cast<__half2*>(&vr.y));
            a0 = fmaf(nf, pa.x, a0);
            a1 = fmaf(nf, pa.y, a1);
            a2 = fmaf(nf, pb.x, a2);
            a3 = fmaf(nf, pb.y, a3);
        }
    }

    if (mode != 2) {
        __half2 ha = __floats2half2_rn(a0, a1);
        __half2 hb = __floats2half2_rn(a2, a3);
        uint2 w;
        w.x = *reinterpret_cast<unsigned*>(&ha);
        w.y = *reinterpret_cast<unsigned*>(&hb);
        xNew[o] = w;
    } else {
        int fo = node * 32 + glane * 2;
        float2 ea = __ldg(&emb2[fo]);
        float2 eb = __ldg(&emb2[fo + 1]);
        uint2 x1r = __ldg(&x1h[o]);
        float2 ba = __half22float2(*reinterpret_cast<__half2*>(&x1r.x));
        float2 bb = __half22float2(*reinterpret_cast<__half2*>(&x1r.y));
        out2[fo] = make_float2((ea.x + ba.x + va.x + a0) * 0.25f,
                               (ea.y + ba.y + va.y + a1) * 0.25f);
        out2[fo + 1] = make_float2((eb.x + bb.x + vb.x + a2) * 0.25f,
                                   (eb.y + bb.y + vb.y + a3) * 0.25f);
    }
}

// ---------------------------------------------------------------------------
extern "C" void kernel_launch(void* const* d_in, const int* in_sizes, int n_in,
                              void* d_out, int out_size) {
    // Bind inputs by unique element count (robust to metadata ordering).
    const float* emb = nullptr;   // 6,400,000 f32
    const float* ew = nullptr;    // 1,600,000 f32
    const void* idx = nullptr;    // 3,200,000 elems (int32 or int64, detected)
    for (int i = 0; i < n_in; i++) {
        if (in_sizes[i] == ND) emb = (const float*)d_in[i];
        else if (in_sizes[i] == EE) ew = (const float*)d_in[i];
        else if (in_sizes[i] == 2 * EE) idx = d_in[i];
    }
    if (!emb) emb = (const float*)d_in[0];
    if (!ew) ew = (const float*)d_in[1];
    if (!idx) idx = d_in[2];

    float2* out2 = (float2*)d_out;

    uint2* h0;
    uint2* h1;
    uint2* h2;
    cudaGetSymbolAddress((void**)&h0, g_h0);
    cudaGetSymbolAddress((void**)&h1, g_h1);
    cudaGetSymbolAddress((void**)&h2, g_h2);

    const int T = 256;
    const int gC = (ND4 + T - 1) / T;           // 6250 (also covers NN init)
    const int gE4 = (EE / 4 + T - 1) / T;       // 1563
    const int gE2 = (EE / 2 + T - 1) / T;       // 3125
    const int gL = NN / 16;                     // 6250 (16 groups/block)

    // Precompute: init+h0, degrees, scan(+dinv), CSR fill  (4 launches)
    k_init<<<gC, T>>>(idx, (const float4*)emb);
    k_count<<<gE4, T>>>(idx);
    k_scan<<<NB, T>>>();
    k_fill<<<gE2, T>>>(idx, ew);

    // Layer 1: x1 <- A @ x0
    k_layer<<<gL, T>>>(h0, h1, nullptr, nullptr, nullptr, 0);
    // Layer 2: x2 <- A @ x1
    k_layer<<<gL, T>>>(h1, h2, nullptr, nullptr, nullptr, 1);
    // Layer 3: out = (x0 + x1 + x2 + A @ x2) / 4   (fp32 out)
    k_layer<<<gL, T>>>(h2, nullptr, (const float2*)emb, h1, out2, 2);
}

// round 9
// speedup vs baseline: 1.2542x; 1.1295x over previous
#include <cuda_runtime.h>
#include <cuda_fp16.h>
#include <cstdint>

// LightGCN propagation: N=100000, E=1600000, D=64, L=3.
// out = (x0 + x1 + x2 + x3)/4, x_{l+1} = A_norm @ x_l (with self loops).
//
// R9: (a) rank-based CSR fill — k_count's indeg atomic return IS the bucket
// rank, so k_fill has no atomics (pos = start[dst] + rank); (b) layer inner
// loop software-pipelined 2 edges deep (2 gather LDGs in flight per exposed
// chain). 16-lane groups (1 shfl-pair / 2 edges), fp16 rows, fp32 accum.

#define NN 100000
#define EE 1600000
#define DD 64
#define ND (NN * DD)       // 6,400,000 floats
#define ND4 (ND / 4)       // 1,600,000
#define NB 391             // ceil(NN / 256)

// Scratch (allocation-free: __device__ globals)
__device__ int g_is32;
__device__ int g_base;           // atomic cursor for scan block bases
__device__ float g_deg[NN];      // source-occurrence degree (incl. self loop)
__device__ float g_dinv[NN];
__device__ int g_indeg[NN];      // destination in-degree (excl. self loop)
__device__ int g_rank[EE];       // edge's arrival rank within its dst bucket
__device__ int g_start[NN];      // CSR bucket start (by destination)
__device__ uint2 g_csr[EE];      // packed (src, norm_bits), grouped by dst
__device__ uint2 g_h0[ND4];      // x0 (emb) as 2x half2 per uint2
__device__ uint2 g_h1[ND4];      // x1
__device__ uint2 g_h2[ND4];      // x2

// ---------------------------------------------------------------------------
// Init: zero degrees, detect index dtype (JAX w/o x64 demotes int64 -> int32;
// element counts are identical, so sample values), convert emb -> fp16.
// ---------------------------------------------------------------------------
__global__ __launch_bounds__(256) void k_init(const void* __restrict__ idx,
                                              const float4* __restrict__ emb4) {
    int i = blockIdx.x * blockDim.x + threadIdx.x;
    if (i < NN) {
        g_deg[i] = 1.0f;   // self loop contributes 1 to every degree
        g_indeg[i] = 0;
    }
    if (i == 0) {
        g_base = 0;
        const long long* p = (const long long*)idx;
        int is64 = 1;
        for (int k = 0; k < 256; k++) {
            long long v = p[k];
            if (v < 0 || v >= (long long)NN) { is64 = 0; break; }
        }
        g_is32 = !is64;
    }
    if (i < ND4) {
        float4 v = __ldg(&emb4[i]);
        __half2 a = __floats2half2_rn(v.x, v.y);
        __half2 b = __floats2half2_rn(v.z, v.w);
        uint2 pck;
        pck.x = *reinterpret_cast<unsigned*>(&a);
        pck.y = *reinterpret_cast<unsigned*>(&b);
        g_h0[i] = pck;
    }
}

// 4 edges per thread. indeg atomic RETURN VALUE = rank within dst bucket,
// stored coalesced (int4) for the atomic-free fill.
__global__ __launch_bounds__(256) void k_count(const void* __restrict__ idx) {
    int t = blockIdx.x * blockDim.x + threadIdx.x;
    int e = t * 4;
    if (e >= EE) return;
    int s0, s1, s2, s3, d0, d1, d2, d3;
    if (g_is32) {
        const int4* p = (const int4*)idx;
        int4 s = __ldg(&p[t]);
        int4 d = __ldg(&p[EE / 4 + t]);
        s0 = s.x; s1 = s.y; s2 = s.z; s3 = s.w;
        d0 = d.x; d1 = d.y; d2 = d.z; d3 = d.w;
    } else {
        const long long* p = (const long long*)idx;
        s0 = (int)p[e];      s1 = (int)p[e + 1];
        s2 = (int)p[e + 2];  s3 = (int)p[e + 3];
        d0 = (int)p[EE + e];     d1 = (int)p[EE + e + 1];
        d2 = (int)p[EE + e + 2]; d3 = (int)p[EE + e + 3];
    }
    atomicAdd(&g_deg[s0], 1.0f); atomicAdd(&g_deg[s1], 1.0f);
    atomicAdd(&g_deg[s2], 1.0f); atomicAdd(&g_deg[s3], 1.0f);
    int4 r;
    r.x = atomicAdd(&g_indeg[d0], 1);
    r.y = atomicAdd(&g_indeg[d1], 1);
    r.z = atomicAdd(&g_indeg[d2], 1);
    r.w = atomicAdd(&g_indeg[d3], 1);
    reinterpret_cast<int4*>(g_rank)[t] = r;
}

// ---------------------------------------------------------------------------
// Single-kernel scan: intra-block prefix of indeg; block base via atomic
// reservation (bucket order across blocks is arbitrary — layers use
// start+indeg, never start[node+1]). Also computes dinv.
// ---------------------------------------------------------------------------
__global__ __launch_bounds__(256) void k_scan() {
    __shared__ int sh[256];
    __shared__ int sbase;
    int i = blockIdx.x * 256 + threadIdx.x;
    int v = (i < NN) ? g_indeg[i] : 0;
    if (i < NN) {
        float d = g_deg[i];
        g_dinv[i] = (d > 0.0f) ? rsqrtf(d) : 0.0f;
    }
    sh[threadIdx.x] = v;
    __syncthreads();
    for (int off = 1; off < 256; off <<= 1) {
        int t = (threadIdx.x >= off) ? sh[threadIdx.x - off] : 0;
        __syncthreads();
        sh[threadIdx.x] += t;
        __syncthreads();
    }
    if (threadIdx.x == 255) sbase = atomicAdd(&g_base, sh[255]);
    __syncthreads();
    if (i < NN) g_start[i] = sbase + sh[threadIdx.x] - v;
}

// Fill CSR, NO atomics: pos = start[dst] + rank[e]. 4 edges per thread.
__global__ __launch_bounds__(256) void k_fill(const void* __restrict__ idx,
                                              const float* __restrict__ w) {
    int t = blockIdx.x * blockDim.x + threadIdx.x;
    int e = t * 4;
    if (e >= EE) return;
    int s0, s1, s2, s3, d0, d1, d2, d3;
    if (g_is32) {
        const int4* p = (const int4*)idx;
        int4 s = __ldg(&p[t]);
        int4 d = __ldg(&p[EE / 4 + t]);
        s0 = s.x; s1 = s.y; s2 = s.z; s3 = s.w;
        d0 = d.x; d1 = d.y; d2 = d.z; d3 = d.w;
    } else {
        const long long* p = (const long long*)idx;
        s0 = (int)p[e];      s1 = (int)p[e + 1];
        s2 = (int)p[e + 2];  s3 = (int)p[e + 3];
        d0 = (int)p[EE + e];     d1 = (int)p[EE + e + 1];
        d2 = (int)p[EE + e + 2]; d3 = (int)p[EE + e + 3];
    }
    float4 wv = __ldg((const float4*)(w + e));
    int4 r = __ldg(&reinterpret_cast<const int4*>(g_rank)[t]);
    float n0 = g_dinv[s0] * wv.x * g_dinv[d0];
    float n1 = g_dinv[s1] * wv.y * g_dinv[d1];
    float n2 = g_dinv[s2] * wv.z * g_dinv[d2];
    float n3 = g_dinv[s3] * wv.w * g_dinv[d3];
    g_csr[g_start[d0] + r.x] = make_uint2((unsigned)s0, __float_as_uint(n0));
    g_csr[g_start[d1] + r.y] = make_uint2((unsigned)s1, __float_as_uint(n1));
    g_csr[g_start[d2] + r.z] = make_uint2((unsigned)s2, __float_as_uint(n2));
    g_csr[g_start[d3] + r.w] = make_uint2((unsigned)s3, __float_as_uint(n3));
}

// ---------------------------------------------------------------------------
// Layer kernel: 16-lane group per node (2 nodes/warp). Lane owns uint2 =
// 4 features (fp16). Width-16 shfls serve both groups (1 shfl-pair / 2 edges).
// Inner loop pipelined 2 edges deep: both gather LDGs issue before either
// consumer, halving exposed L2 latency. Warp-uniform trip counts. fp32 accum.
//   acc = dinv[n]^2 * xOld[n] + sum_{e in CSR[n]} norm[e] * xOld[src[e]]
// mode 0/1: xNew = half(acc)
// mode 2:   out = (emb + x1 + xOld + acc) * 0.25 in fp32 (xOld == x2)
// ---------------------------------------------------------------------------
__global__ __launch_bounds__(256) void k_layer(const uint2* __restrict__ xOld,
                                               uint2* __restrict__ xNew,
                                               const float2* __restrict__ emb2,
                                               const uint2* __restrict__ x1h,
                                               float2* __restrict__ out2,
                                               int mode) {
    int glane = threadIdx.x & 15;
    int node = blockIdx.x * 16 + (threadIdx.x >> 4);  // grid covers exactly NN

    int start = g_start[node];
    int m = g_indeg[node];
    float s = g_dinv[node];
    s *= s;

    int o = node * 16 + glane;
    uint2 r0 = xOld[o];
    float2 va = __half22float2(*reinterpret_cast<__half2*>(&r0.x));
    float2 vb = __half22float2(*reinterpret_cast<__half2*>(&r0.y));
    float a0 = s * va.x, a1 = s * va.y, a2 = s * vb.x, a3 = s * vb.y;

    // Warp-uniform iteration bound across the 2 groups in this warp.
    int mo = __shfl_xor_sync(0xFFFFFFFFu, m, 16);
    int maxm = m > mo ? m : mo;

    for (int base = 0; base < maxm; base += 16) {
        uint2 ed = make_uint2(0u, 0u);
        if (base + glane < m) ed = __ldg(&g_csr[start + base + glane]);
        int t = maxm - base;
        if (t > 16) t = 16;
        int j = 0;
        for (; j + 2 <= t; j += 2) {
            unsigned sj0 = __shfl_sync(0xFFFFFFFFu, ed.x, j, 16);
            unsigned nj0 = __shfl_sync(0xFFFFFFFFu, ed.y, j, 16);
            unsigned sj1 = __shfl_sync(0xFFFFFFFFu, ed.x, j + 1, 16);
            unsigned nj1 = __shfl_sync(0xFFFFFFFFu, ed.y, j + 1, 16);
            uint2 vr0 = __ldg(&xOld[sj0 * 16 + glane]);
            uint2 vr1 = __ldg(&xOld[sj1 * 16 + glane]);
            float n0 = __uint_as_float(nj0);
            float n1 = __uint_as_float(nj1);
            float2 p0a = __half22float2(*reinterpret_cast<__half2*>(&vr0.x));
            float2 p0b = __half22float2(*reinterpret_cast<__half2*>(&vr0.y));
            float2 p1a = __half22float2(*reinterpret_cast<__half2*>(&vr1.x));
            float2 p1b = __half22float2(*reinterpret_cast<__half2*>(&vr1.y));
            a0 = fmaf(n0, p0a.x, a0); a1 = fmaf(n0, p0a.y, a1);
            a2 = fmaf(n0, p0b.x, a2); a3 = fmaf(n0, p0b.y, a3);
            a0 = fmaf(n1, p1a.x, a0); a1 = fmaf(n1, p1a.y, a1);
            a2 = fmaf(n1, p1b.x, a2); a3 = fmaf(n1, p1b.y, a3);
        }
        if (j < t) {
            unsigned sj = __shfl_sync(0xFFFFFFFFu, ed.x, j, 16);
            float nf = __uint_as_float(__shfl_sync(0xFFFFFFFFu, ed.y, j, 16));
            uint2 vr = __ldg(&xOld[sj * 16 + glane]);
            float2 pa = __half22float2(*reinterpret_cast<__half2*>(&vr.x));
            float2 pb = __half22float2(*reinterpret_cast<__half2*>(&vr.y));
            a0 = fmaf(nf, pa.x, a0); a1 = fmaf(nf, pa.y, a1);
            a2 = fmaf(nf, pb.x, a2); a3 = fmaf(nf, pb.y, a3);
        }
    }

    if (mode != 2) {
        __half2 ha = __floats2half2_rn(a0, a1);
        __half2 hb = __floats2half2_rn(a2, a3);
        uint2 w;
        w.x = *reinterpret_cast<unsigned*>(&ha);
        w.y = *reinterpret_cast<unsigned*>(&hb);
        xNew[o] = w;
    } else {
        int fo = node * 32 + glane * 2;
        float2 ea = __ldg(&emb2[fo]);
        float2 eb = __ldg(&emb2[fo + 1]);
        uint2 x1r = __ldg(&x1h[o]);
        float2 ba = __half22float2(*reinterpret_cast<__half2*>(&x1r.x));
        float2 bb = __half22float2(*reinterpret_cast<__half2*>(&x1r.y));
        out2[fo] = make_float2((ea.x + ba.x + va.x + a0) * 0.25f,
                               (ea.y + ba.y + va.y + a1) * 0.25f);
        out2[fo + 1] = make_float2((eb.x + bb.x + vb.x + a2) * 0.25f,
                                   (eb.y + bb.y + vb.y + a3) * 0.25f);
    }
}

// ---------------------------------------------------------------------------
extern "C" void kernel_launch(void* const* d_in, const int* in_sizes, int n_in,
                              void* d_out, int out_size) {
    // Bind inputs by unique element count (robust to metadata ordering).
    const float* emb = nullptr;   // 6,400,000 f32
    const float* ew = nullptr;    // 1,600,000 f32
    const void* idx = nullptr;    // 3,200,000 elems (int32 or int64, detected)
    for (int i = 0; i < n_in; i++) {
        if (in_sizes[i] == ND) emb = (const float*)d_in[i];
        else if (in_sizes[i] == EE) ew = (const float*)d_in[i];
        else if (in_sizes[i] == 2 * EE) idx = d_in[i];
    }
    if (!emb) emb = (const float*)d_in[0];
    if (!ew) ew = (const float*)d_in[1];
    if (!idx) idx = d_in[2];

    float2* out2 = (float2*)d_out;

    uint2* h0;
    uint2* h1;
    uint2* h2;
    cudaGetSymbolAddress((void**)&h0, g_h0);
    cudaGetSymbolAddress((void**)&h1, g_h1);
    cudaGetSymbolAddress((void**)&h2, g_h2);

    const int T = 256;
    const int gC = (ND4 + T - 1) / T;           // 6250 (also covers NN init)
    const int gE4 = (EE / 4 + T - 1) / T;       // 1563
    const int gL = NN / 16;                     // 6250 (16 groups/block)

    // Precompute: init+h0, degrees+ranks, scan(+dinv), CSR fill (4 launches)
    k_init<<<gC, T>>>(idx, (const float4*)emb);
    k_count<<<gE4, T>>>(idx);
    k_scan<<<NB, T>>>();
    k_fill<<<gE4, T>>>(idx, ew);

    // Layer 1: x1 <- A @ x0
    k_layer<<<gL, T>>>(h0, h1, nullptr, nullptr, nullptr, 0);
    // Layer 2: x2 <- A @ x1
    k_layer<<<gL, T>>>(h1, h2, nullptr, nullptr, nullptr, 1);
    // Layer 3: out = (x0 + x1 + x2 + A @ x2) / 4   (fp32 out)
    k_layer<<<gL, T>>>(h2, nullptr, (const float2*)emb, h1, out2, 2);
}

// round 10
// speedup vs baseline: 1.3435x; 1.0712x over previous
#include <cuda_runtime.h>
#include <cuda_fp16.h>
#include <cstdint>

// LightGCN propagation: N=100000, E=1600000, D=64, L=3.
// out = (x0 + x1 + x2 + x3)/4, x_{l+1} = A_norm @ x_l (with self loops).
//
// R10: pre-scaled rows z_l = dinv * x_l turn the recurrence into
//   z_{l+1}[d] = dinv[d]^2 * ( z_l[d] + sum_e w_e * z_l[src_e] )
// so the CSR stores just (src, w) and k_fill has NO random loads (its dinv
// gathers were the R9 bottleneck: issue=3.8%, 27.6us). x_l = rdinv * z_l
// recovers the per-layer outputs for the final mean. fp16 z rows, fp32 accum.

#define NN 100000
#define EE 1600000
#define DD 64
#define ND (NN * DD)       // 6,400,000 floats
#define ND4 (ND / 4)       // 1,600,000
#define NB 391             // ceil(NN / 256)

// Scratch (allocation-free: __device__ globals)
__device__ int g_is32;
__device__ int g_base;           // atomic cursor for scan block bases
__device__ float g_deg[NN];      // source-occurrence degree (incl. self loop)
__device__ float g_dinv[NN];     // 1/sqrt(deg)
__device__ float g_rdinv[NN];    // sqrt(deg)
__device__ int g_indeg[NN];      // destination in-degree (excl. self loop)
__device__ int g_rank[EE];       // edge's arrival rank within its dst bucket
__device__ int g_start[NN];      // CSR bucket start (by destination)
__device__ uint2 g_csr[EE];      // packed (src, w_bits), grouped by dst
__device__ uint2 g_z0[ND4];      // z0 = dinv*emb as 2x half2 per uint2
__device__ uint2 g_z1[ND4];      // z1
__device__ uint2 g_z2[ND4];      // z2

// ---------------------------------------------------------------------------
// Init: degrees + index-dtype detection (JAX w/o x64 demotes int64 -> int32;
// element counts are identical, so sample values to disambiguate).
// ---------------------------------------------------------------------------
__global__ __launch_bounds__(256) void k_init(const void* __restrict__ idx) {
    int i = blockIdx.x * blockDim.x + threadIdx.x;
    if (i < NN) {
        g_deg[i] = 1.0f;   // self loop contributes 1 to every degree
        g_indeg[i] = 0;
    }
    if (i == 0) {
        g_base = 0;
        const long long* p = (const long long*)idx;
        int is64 = 1;
        for (int k = 0; k < 256; k++) {
            long long v = p[k];
            if (v < 0 || v >= (long long)NN) { is64 = 0; break; }
        }
        g_is32 = !is64;
    }
}

// 4 edges per thread. indeg atomic RETURN VALUE = rank within dst bucket,
// stored coalesced (int4) for the atomic-free fill.
__global__ __launch_bounds__(256) void k_count(const void* __restrict__ idx) {
    int t = blockIdx.x * blockDim.x + threadIdx.x;
    int e = t * 4;
    if (e >= EE) return;
    int s0, s1, s2, s3, d0, d1, d2, d3;
    if (g_is32) {
        const int4* p = (const int4*)idx;
        int4 s = __ldg(&p[t]);
        int4 d = __ldg(&p[EE / 4 + t]);
        s0 = s.x; s1 = s.y; s2 = s.z; s3 = s.w;
        d0 = d.x; d1 = d.y; d2 = d.z; d3 = d.w;
    } else {
        const long long* p = (const long long*)idx;
        s0 = (int)p[e];      s1 = (int)p[e + 1];
        s2 = (int)p[e + 2];  s3 = (int)p[e + 3];
        d0 = (int)p[EE + e];     d1 = (int)p[EE + e + 1];
        d2 = (int)p[EE + e + 2]; d3 = (int)p[EE + e + 3];
    }
    atomicAdd(&g_deg[s0], 1.0f); atomicAdd(&g_deg[s1], 1.0f);
    atomicAdd(&g_deg[s2], 1.0f); atomicAdd(&g_deg[s3], 1.0f);
    int4 r;
    r.x = atomicAdd(&g_indeg[d0], 1);
    r.y = atomicAdd(&g_indeg[d1], 1);
    r.z = atomicAdd(&g_indeg[d2], 1);
    r.w = atomicAdd(&g_indeg[d3], 1);
    reinterpret_cast<int4*>(g_rank)[t] = r;
}

// ---------------------------------------------------------------------------
// Single-kernel scan: intra-block prefix of indeg; block base via atomic
// reservation (bucket order across blocks is arbitrary — layers use
// start+indeg, never start[node+1]). Also computes dinv and rdinv.
// ---------------------------------------------------------------------------
__global__ __launch_bounds__(256) void k_scan() {
    __shared__ int sh[256];
    __shared__ int sbase;
    int i = blockIdx.x * 256 + threadIdx.x;
    int v = (i < NN) ? g_indeg[i] : 0;
    if (i < NN) {
        float d = g_deg[i];
        g_dinv[i] = rsqrtf(d);      // deg >= 1 always (self loop)
        g_rdinv[i] = sqrtf(d);
    }
    sh[threadIdx.x] = v;
    __syncthreads();
    for (int off = 1; off < 256; off <<= 1) {
        int t = (threadIdx.x >= off) ? sh[threadIdx.x - off] : 0;
        __syncthreads();
        sh[threadIdx.x] += t;
        __syncthreads();
    }
    if (threadIdx.x == 255) sbase = atomicAdd(&g_base, sh[255]);
    __syncthreads();
    if (i < NN) g_start[i] = sbase + sh[threadIdx.x] - v;
}

// ---------------------------------------------------------------------------
// Fill CSR (no atomics, NO random loads: pos = start[dst] + rank[e], entry is
// (src, w)) + convert emb -> z0 = dinv * emb in fp16. One fused launch; grid
// covers ND4; first EE/4 threads also fill 4 edges each.
// ---------------------------------------------------------------------------
__global__ __launch_bounds__(256) void k_fillz(const void* __restrict__ idx,
                                               const float* __restrict__ w,
                                               const float4* __restrict__ emb4) {
    int t = blockIdx.x * blockDim.x + threadIdx.x;
    if (t < ND4) {
        int node = t >> 4;
        float dv = g_dinv[node];
        float4 v = __ldg(&emb4[t]);
        __half2 a = __floats2half2_rn(dv * v.x, dv * v.y);
        __half2 b = __floats2half2_rn(dv * v.z, dv * v.w);
        uint2 pck;
        pck.x = *reinterpret_cast<unsigned*>(&a);
        pck.y = *reinterpret_cast<unsigned*>(&b);
        g_z0[t] = pck;
    }
    if (t >= EE / 4) return;
    int e = t * 4;
    int s0, s1, s2, s3, d0, d1, d2, d3;
    if (g_is32) {
        const int4* p = (const int4*)idx;
        int4 s = __ldg(&p[t]);
        int4 d = __ldg(&p[EE / 4 + t]);
        s0 = s.x; s1 = s.y; s2 = s.z; s3 = s.w;
        d0 = d.x; d1 = d.y; d2 = d.z; d3 = d.w;
    } else {
        const long long* p = (const long long*)idx;
        s0 = (int)p[e];      s1 = (int)p[e + 1];
        s2 = (int)p[e + 2];  s3 = (int)p[e + 3];
        d0 = (int)p[EE + e];     d1 = (int)p[EE + e + 1];
        d2 = (int)p[EE + e + 2]; d3 = (int)p[EE + e + 3];
    }
    float4 wv = __ldg((const float4*)(w + e));
    int4 r = __ldg(&reinterpret_cast<const int4*>(g_rank)[t]);
    int4 st;
    st.x = __ldg(&g_start[d0]);
    st.y = __ldg(&g_start[d1]);
    st.z = __ldg(&g_start[d2]);
    st.w = __ldg(&g_start[d3]);
    g_csr[st.x + r.x] = make_uint2((unsigned)s0, __float_as_uint(wv.x));
    g_csr[st.y + r.y] = make_uint2((unsigned)s1, __float_as_uint(wv.y));
    g_csr[st.z + r.z] = make_uint2((unsigned)s2, __float_as_uint(wv.z));
    g_csr[st.w + r.w] = make_uint2((unsigned)s3, __float_as_uint(wv.w));
}

// ---------------------------------------------------------------------------
// Layer kernel: 16-lane group per node (2 nodes/warp). Lane owns uint2 =
// 4 features (fp16 z). Width-16 shfls serve both groups. Batch-2 pipeline
// (2 gather LDGs in flight). fp32 accumulation.
//   S = z_old[d] + sum_e w_e * z_old[src_e]
// mode 0/1: z_new[d] = half( dinv[d]^2 * S )
// mode 2:   out = (emb + rdinv*z1 + rdinv*z_old + dinv*S) * 0.25   (z_old==z2)
// ---------------------------------------------------------------------------
__global__ __launch_bounds__(256) void k_layer(const uint2* __restrict__ zOld,
                                               uint2* __restrict__ zNew,
                                               const float2* __restrict__ emb2,
                                               const uint2* __restrict__ z1p,
                                               float2* __restrict__ out2,
                                               int mode) {
    int glane = threadIdx.x & 15;
    int node = blockIdx.x * 16 + (threadIdx.x >> 4);  // grid covers exactly NN

    int start = g_start[node];
    int m = g_indeg[node];
    float dv = g_dinv[node];

    int o = node * 16 + glane;
    uint2 r0 = zOld[o];
    float2 va = __half22float2(*reinterpret_cast<__half2*>(&r0.x));
    float2 vb = __half22float2(*reinterpret_cast<__half2*>(&r0.y));
    float a0 = va.x, a1 = va.y, a2 = vb.x, a3 = vb.y;  // S starts at z_old[d]

    // Warp-uniform iteration bound across the 2 groups in this warp.
    int mo = __shfl_xor_sync(0xFFFFFFFFu, m, 16);
    int maxm = m > mo ? m : mo;

    for (int base = 0; base < maxm; base += 16) {
        uint2 ed = make_uint2(0u, 0u);
        if (base + glane < m) ed = __ldg(&g_csr[start + base + glane]);
        int t = maxm - base;
        if (t > 16) t = 16;
        int j = 0;
        for (; j + 2 <= t; j += 2) {
            unsigned sj0 = __shfl_sync(0xFFFFFFFFu, ed.x, j, 16);
            unsigned nj0 = __shfl_sync(0xFFFFFFFFu, ed.y, j, 16);
            unsigned sj1 = __shfl_sync(0xFFFFFFFFu, ed.x, j + 1, 16);
            unsigned nj1 = __shfl_sync(0xFFFFFFFFu, ed.y, j + 1, 16);
            uint2 vr0 = __ldg(&zOld[sj0 * 16 + glane]);
            uint2 vr1 = __ldg(&zOld[sj1 * 16 + glane]);
            float n0 = __uint_as_float(nj0);
            float n1 = __uint_as_float(nj1);
            float2 p0a = __half22float2(*reinterpret_cast<__half2*>(&vr0.x));
            float2 p0b = __half22float2(*reinterpret_cast<__half2*>(&vr0.y));
            float2 p1a = __half22float2(*reinterpret_cast<__half2*>(&vr1.x));
            float2 p1b = __half22float2(*reinterpret_cast<__half2*>(&vr1.y));
            a0 = fmaf(n0, p0a.x, a0); a1 = fmaf(n0, p0a.y, a1);
            a2 = fmaf(n0, p0b.x, a2); a3 = fmaf(n0, p0b.y, a3);
            a0 = fmaf(n1, p1a.x, a0); a1 = fmaf(n1, p1a.y, a1);
            a2 = fmaf(n1, p1b.x, a2); a3 = fmaf(n1, p1b.y, a3);
        }
        if (j < t) {
            unsigned sj = __shfl_sync(0xFFFFFFFFu, ed.x, j, 16);
            float nf = __uint_as_float(__shfl_sync(0xFFFFFFFFu, ed.y, j, 16));
            uint2 vr = __ldg(&zOld[sj * 16 + glane]);
            float2 pa = __half22float2(*reinterpret_cast<__half2*>(&vr.x));
            float2 pb = __half22float2(*reinterpret_cast<__half2*>(&vr.y));
            a0 = fmaf(nf, pa.x, a0); a1 = fmaf(nf, pa.y, a1);
            a2 = fmaf(nf, pb.x, a2); a3 = fmaf(nf, pb.y, a3);
        }
    }

    if (mode != 2) {
        float s2 = dv * dv;
        __half2 ha = __floats2half2_rn(s2 * a0, s2 * a1);
        __half2 hb = __floats2half2_rn(s2 * a2, s2 * a3);
        uint2 wv;
        wv.x = *reinterpret_cast<unsigned*>(&ha);
        wv.y = *reinterpret_cast<unsigned*>(&hb);
        zNew[o] = wv;
    } else {
        float rv = g_rdinv[node];
        int fo = node * 32 + glane * 2;
        float2 ea = __ldg(&emb2[fo]);
        float2 eb = __ldg(&emb2[fo + 1]);
        uint2 z1r = __ldg(&z1p[o]);
        float2 ba = __half22float2(*reinterpret_cast<__half2*>(&z1r.x));
        float2 bb = __half22float2(*reinterpret_cast<__half2*>(&z1r.y));
        // x1 = rdinv*z1, x2 = rdinv*z2(=zOld row), x3 = dinv*S
        out2[fo] = make_float2(
            (ea.x + rv * (ba.x + va.x) + dv * a0) * 0.25f,
            (ea.y + rv * (ba.y + va.y) + dv * a1) * 0.25f);
        out2[fo + 1] = make_float2(
            (eb.x + rv * (bb.x + vb.x) + dv * a2) * 0.25f,
            (eb.y + rv * (bb.y + vb.y) + dv * a3) * 0.25f);
    }
}

// ---------------------------------------------------------------------------
extern "C" void kernel_launch(void* const* d_in, const int* in_sizes, int n_in,
                              void* d_out, int out_size) {
    // Bind inputs by unique element count (robust to metadata ordering).
    const float* emb = nullptr;   // 6,400,000 f32
    const float* ew = nullptr;    // 1,600,000 f32
    const void* idx = nullptr;    // 3,200,000 elems (int32 or int64, detected)
    for (int i = 0; i < n_in; i++) {
        if (in_sizes[i] == ND) emb = (const float*)d_in[i];
        else if (in_sizes[i] == EE) ew = (const float*)d_in[i];
        else if (in_sizes[i] == 2 * EE) idx = d_in[i];
    }
    if (!emb) emb = (const float*)d_in[0];
    if (!ew) ew = (const float*)d_in[1];
    if (!idx) idx = d_in[2];

    float2* out2 = (float2*)d_out;

    uint2* z0;
    uint2* z1;
    uint2* z2;
    cudaGetSymbolAddress((void**)&z0, g_z0);
    cudaGetSymbolAddress((void**)&z1, g_z1);
    cudaGetSymbolAddress((void**)&z2, g_z2);

    const int T = 256;
    const int gN = (NN + T - 1) / T;            // 391
    const int gC = (ND4 + T - 1) / T;           // 6250
    const int gE4 = (EE / 4 + T - 1) / T;       // 1563
    const int gL = NN / 16;                     // 6250 (16 groups/block)

    // Precompute: init, degrees+ranks, scan(+dinv,rdinv), fill+z0 (4 launches)
    k_init<<<gN, T>>>(idx);
    k_count<<<gE4, T>>>(idx);
    k_scan<<<NB, T>>>();
    k_fillz<<<gC, T>>>(idx, ew, (const float4*)emb);

    // Layer 1: z1 <- dinv^2 (z0 + A_w z0)
    k_layer<<<gL, T>>>(z0, z1, nullptr, nullptr, nullptr, 0);
    // Layer 2: z2
    k_layer<<<gL, T>>>(z1, z2, nullptr, nullptr, nullptr, 1);
    // Layer 3: out = (x0 + x1 + x2 + x3) / 4  (fp32 out)
    k_layer<<<gL, T>>>(z2, nullptr, (const float2*)emb, z1, out2, 2);
}

// round 11
// speedup vs baseline: 1.3577x; 1.0106x over previous
#include <cuda_runtime.h>
#include <cuda_fp16.h>
#include <cstdint>

// LightGCN propagation: N=100000, E=1600000, D=64, L=3.
// out = (x0 + x1 + x2 + x3)/4, x_{l+1} = A_norm @ x_l (with self loops).
//
// R11: z-recurrence (z = dinv*x) kept; layer switched to 8-lane groups
// (4 nodes/warp), lane owns uint4 = 8 fp16 features -> LDG.128 gathers
// (0.25 warp-LDG/edge) and width-8 shfls serving 4 groups (0.25 shfl-pair
// per edge). Batch-2 software pipeline, fp32 accumulation.

#define NN 100000
#define EE 1600000
#define DD 64
#define ND (NN * DD)       // 6,400,000 floats
#define ND8 (ND / 8)       // 800,000 uint4 (fp16 rows)
#define NB 391             // ceil(NN / 256)

// Scratch (allocation-free: __device__ globals)
__device__ int g_is32;
__device__ int g_base;           // atomic cursor for scan block bases
__device__ float g_deg[NN];      // source-occurrence degree (incl. self loop)
__device__ float g_dinv[NN];     // 1/sqrt(deg)
__device__ float g_rdinv[NN];    // sqrt(deg)
__device__ int g_indeg[NN];      // destination in-degree (excl. self loop)
__device__ int g_rank[EE];       // edge's arrival rank within its dst bucket
__device__ int g_start[NN];      // CSR bucket start (by destination)
__device__ uint2 g_csr[EE];      // packed (src, w_bits), grouped by dst
__device__ uint4 g_z0[ND8];      // z0 = dinv*emb, 8 halves per uint4
__device__ uint4 g_z1[ND8];      // z1
__device__ uint4 g_z2[ND8];      // z2

// ---------------------------------------------------------------------------
// Init: degrees + index-dtype detection (JAX w/o x64 demotes int64 -> int32;
// element counts are identical, so sample values to disambiguate).
// ---------------------------------------------------------------------------
__global__ __launch_bounds__(256) void k_init(const void* __restrict__ idx) {
    int i = blockIdx.x * blockDim.x + threadIdx.x;
    if (i < NN) {
        g_deg[i] = 1.0f;   // self loop contributes 1 to every degree
        g_indeg[i] = 0;
    }
    if (i == 0) {
        g_base = 0;
        const long long* p = (const long long*)idx;
        int is64 = 1;
        for (int k = 0; k < 256; k++) {
            long long v = p[k];
            if (v < 0 || v >= (long long)NN) { is64 = 0; break; }
        }
        g_is32 = !is64;
    }
}

// 4 edges per thread. indeg atomic RETURN VALUE = rank within dst bucket,
// stored coalesced (int4) for the atomic-free fill.
__global__ __launch_bounds__(256) void k_count(const void* __restrict__ idx) {
    int t = blockIdx.x * blockDim.x + threadIdx.x;
    int e = t * 4;
    if (e >= EE) return;
    int s0, s1, s2, s3, d0, d1, d2, d3;
    if (g_is32) {
        const int4* p = (const int4*)idx;
        int4 s = __ldg(&p[t]);
        int4 d = __ldg(&p[EE / 4 + t]);
        s0 = s.x; s1 = s.y; s2 = s.z; s3 = s.w;
        d0 = d.x; d1 = d.y; d2 = d.z; d3 = d.w;
    } else {
        const long long* p = (const long long*)idx;
        s0 = (int)p[e];      s1 = (int)p[e + 1];
        s2 = (int)p[e + 2];  s3 = (int)p[e + 3];
        d0 = (int)p[EE + e];     d1 = (int)p[EE + e + 1];
        d2 = (int)p[EE + e + 2]; d3 = (int)p[EE + e + 3];
    }
    atomicAdd(&g_deg[s0], 1.0f); atomicAdd(&g_deg[s1], 1.0f);
    atomicAdd(&g_deg[s2], 1.0f); atomicAdd(&g_deg[s3], 1.0f);
    int4 r;
    r.x = atomicAdd(&g_indeg[d0], 1);
    r.y = atomicAdd(&g_indeg[d1], 1);
    r.z = atomicAdd(&g_indeg[d2], 1);
    r.w = atomicAdd(&g_indeg[d3], 1);
    reinterpret_cast<int4*>(g_rank)[t] = r;
}

// ---------------------------------------------------------------------------
// Single-kernel scan: intra-block prefix of indeg; block base via atomic
// reservation (bucket order across blocks is arbitrary — layers use
// start+indeg, never start[node+1]). Also computes dinv and rdinv.
// ---------------------------------------------------------------------------
__global__ __launch_bounds__(256) void k_scan() {
    __shared__ int sh[256];
    __shared__ int sbase;
    int i = blockIdx.x * 256 + threadIdx.x;
    int v = (i < NN) ? g_indeg[i] : 0;
    if (i < NN) {
        float d = g_deg[i];
        g_dinv[i] = rsqrtf(d);      // deg >= 1 always (self loop)
        g_rdinv[i] = sqrtf(d);
    }
    sh[threadIdx.x] = v;
    __syncthreads();
    for (int off = 1; off < 256; off <<= 1) {
        int t = (threadIdx.x >= off) ? sh[threadIdx.x - off] : 0;
        __syncthreads();
        sh[threadIdx.x] += t;
        __syncthreads();
    }
    if (threadIdx.x == 255) sbase = atomicAdd(&g_base, sh[255]);
    __syncthreads();
    if (i < NN) g_start[i] = sbase + sh[threadIdx.x] - v;
}

// ---------------------------------------------------------------------------
// Fill CSR (no atomics: pos = start[dst] + rank[e], entry (src, w)) + convert
// emb -> z0 = dinv*emb (fp16, uint4 granularity). Grid covers ND8 = 800000;
// first EE/4 = 400000 threads also fill 4 edges each.
// ---------------------------------------------------------------------------
__global__ __launch_bounds__(256) void k_fillz(const void* __restrict__ idx,
                                               const float* __restrict__ w,
                                               const float4* __restrict__ emb4) {
    int t = blockIdx.x * blockDim.x + threadIdx.x;
    if (t < ND8) {
        int node = t >> 3;
        float dv = g_dinv[node];
        float4 va = __ldg(&emb4[t * 2]);
        float4 vb = __ldg(&emb4[t * 2 + 1]);
        __half2 h0 = __floats2half2_rn(dv * va.x, dv * va.y);
        __half2 h1 = __floats2half2_rn(dv * va.z, dv * va.w);
        __half2 h2 = __floats2half2_rn(dv * vb.x, dv * vb.y);
        __half2 h3 = __floats2half2_rn(dv * vb.z, dv * vb.w);
        uint4 pck;
        pck.x = *reinterpret_cast<unsigned*>(&h0);
        pck.y = *reinterpret_cast<unsigned*>(&h1);
        pck.z = *reinterpret_cast<unsigned*>(&h2);
        pck.w = *reinterpret_cast<unsigned*>(&h3);
        g_z0[t] = pck;
    }
    if (t >= EE / 4) return;
    int e = t * 4;
    int s0, s1, s2, s3, d0, d1, d2, d3;
    if (g_is32) {
        const int4* p = (const int4*)idx;
        int4 s = __ldg(&p[t]);
        int4 d = __ldg(&p[EE / 4 + t]);
        s0 = s.x; s1 = s.y; s2 = s.z; s3 = s.w;
        d0 = d.x; d1 = d.y; d2 = d.z; d3 = d.w;
    } else {
        const long long* p = (const long long*)idx;
        s0 = (int)p[e];      s1 = (int)p[e + 1];
        s2 = (int)p[e + 2];  s3 = (int)p[e + 3];
        d0 = (int)p[EE + e];     d1 = (int)p[EE + e + 1];
        d2 = (int)p[EE + e + 2]; d3 = (int)p[EE + e + 3];
    }
    float4 wv = __ldg((const float4*)(w + e));
    int4 r = __ldg(&reinterpret_cast<const int4*>(g_rank)[t]);
    int4 st;
    st.x = __ldg(&g_start[d0]);
    st.y = __ldg(&g_start[d1]);
    st.z = __ldg(&g_start[d2]);
    st.w = __ldg(&g_start[d3]);
    g_csr[st.x + r.x] = make_uint2((unsigned)s0, __float_as_uint(wv.x));
    g_csr[st.y + r.y] = make_uint2((unsigned)s1, __float_as_uint(wv.y));
    g_csr[st.z + r.z] = make_uint2((unsigned)s2, __float_as_uint(wv.z));
    g_csr[st.w + r.w] = make_uint2((unsigned)s3, __float_as_uint(wv.w));
}

// Unpack uint4 (8 halves) into 8 floats.
__device__ __forceinline__ void unpack8(uint4 r, float* f) {
    float2 p0 = __half22float2(*reinterpret_cast<__half2*>(&r.x));
    float2 p1 = __half22float2(*reinterpret_cast<__half2*>(&r.y));
    float2 p2 = __half22float2(*reinterpret_cast<__half2*>(&r.z));
    float2 p3 = __half22float2(*reinterpret_cast<__half2*>(&r.w));
    f[0] = p0.x; f[1] = p0.y; f[2] = p1.x; f[3] = p1.y;
    f[4] = p2.x; f[5] = p2.y; f[6] = p3.x; f[7] = p3.y;
}

// ---------------------------------------------------------------------------
// Layer kernel: 8-lane group per node (4 nodes/warp). Lane owns uint4 = 8 fp16
// features. Width-8 shfls serve all 4 groups (0.25 shfl-pair/edge); gather is
// LDG.128 (0.25 warp-LDG/edge). Batch-2 pipeline. Warp-uniform trip count
// (max over 4 groups; padded iters use w=0, row 0, L1-hot). fp32 accum.
//   S = z_old[d] + sum_e w_e * z_old[src_e]
// mode 0/1: z_new[d] = half( dinv[d]^2 * S )
// mode 2:   out = (emb + rdinv*(z1 + z_old) + dinv*S) * 0.25   (z_old==z2)
// ---------------------------------------------------------------------------
__global__ __launch_bounds__(256) void k_layer(const uint4* __restrict__ zOld,
                                               uint4* __restrict__ zNew,
                                               const float4* __restrict__ emb4,
                                               const uint4* __restrict__ z1p,
                                               float4* __restrict__ out4,
                                               int mode) {
    int glane = threadIdx.x & 7;
    int node = blockIdx.x * 32 + (threadIdx.x >> 3);  // grid covers exactly NN

    int start = g_start[node];
    int m = g_indeg[node];
    float dv = g_dinv[node];

    int o = node * 8 + glane;
    float v0[8];
    unpack8(zOld[o], v0);
    float a[8];
    #pragma unroll
    for (int k = 0; k < 8; k++) a[k] = v0[k];  // S starts at z_old[d]

    // Warp-uniform iteration bound across the 4 groups in this warp.
    int m1 = max(m, __shfl_xor_sync(0xFFFFFFFFu, m, 8));
    int maxm = max(m1, __shfl_xor_sync(0xFFFFFFFFu, m1, 16));

    for (int base = 0; base < maxm; base += 8) {
        uint2 ed = make_uint2(0u, 0u);
        if (base + glane < m) ed = __ldg(&g_csr[start + base + glane]);
        int t = maxm - base;
        if (t > 8) t = 8;
        int j = 0;
        for (; j + 2 <= t; j += 2) {
            unsigned sj0 = __shfl_sync(0xFFFFFFFFu, ed.x, j, 8);
            unsigned nj0 = __shfl_sync(0xFFFFFFFFu, ed.y, j, 8);
            unsigned sj1 = __shfl_sync(0xFFFFFFFFu, ed.x, j + 1, 8);
            unsigned nj1 = __shfl_sync(0xFFFFFFFFu, ed.y, j + 1, 8);
            uint4 vr0 = __ldg(&zOld[sj0 * 8 + glane]);
            uint4 vr1 = __ldg(&zOld[sj1 * 8 + glane]);
            float n0 = __uint_as_float(nj0);
            float n1 = __uint_as_float(nj1);
            float f0[8], f1[8];
            unpack8(vr0, f0);
            unpack8(vr1, f1);
            #pragma unroll
            for (int k = 0; k < 8; k++) a[k] = fmaf(n0, f0[k], a[k]);
            #pragma unroll
            for (int k = 0; k < 8; k++) a[k] = fmaf(n1, f1[k], a[k]);
        }
        if (j < t) {
            unsigned sj = __shfl_sync(0xFFFFFFFFu, ed.x, j, 8);
            float nf = __uint_as_float(__shfl_sync(0xFFFFFFFFu, ed.y, j, 8));
            uint4 vr = __ldg(&zOld[sj * 8 + glane]);
            float f[8];
            unpack8(vr, f);
            #pragma unroll
            for (int k = 0; k < 8; k++) a[k] = fmaf(nf, f[k], a[k]);
        }
    }

    if (mode != 2) {
        float s2 = dv * dv;
        __half2 h0 = __floats2half2_rn(s2 * a[0], s2 * a[1]);
        __half2 h1 = __floats2half2_rn(s2 * a[2], s2 * a[3]);
        __half2 h2 = __floats2half2_rn(s2 * a[4], s2 * a[5]);
        __half2 h3 = __floats2half2_rn(s2 * a[6], s2 * a[7]);
        uint4 wv;
        wv.x = *reinterpret_cast<unsigned*>(&h0);
        wv.y = *reinterpret_cast<unsigned*>(&h1);
        wv.z = *reinterpret_cast<unsigned*>(&h2);
        wv.w = *reinterpret_cast<unsigned*>(&h3);
        zNew[o] = wv;
    } else {
        float rv = g_rdinv[node];
        float z1f[8];
        unpack8(__ldg(&z1p[o]), z1f);
        float4 ea = __ldg(&emb4[o * 2]);
        float4 eb = __ldg(&emb4[o * 2 + 1]);
        // x1 = rdinv*z1, x2 = rdinv*z2(=v0), x3 = dinv*S
        float4 oa, ob;
        oa.x = (ea.x + rv * (z1f[0] + v0[0]) + dv * a[0]) * 0.25f;
        oa.y = (ea.y + rv * (z1f[1] + v0[1]) + dv * a[1]) * 0.25f;
        oa.z = (ea.z + rv * (z1f[2] + v0[2]) + dv * a[2]) * 0.25f;
        oa.w = (ea.w + rv * (z1f[3] + v0[3]) + dv * a[3]) * 0.25f;
        ob.x = (eb.x + rv * (z1f[4] + v0[4]) + dv * a[4]) * 0.25f;
        ob.y = (eb.y + rv * (z1f[5] + v0[5]) + dv * a[5]) * 0.25f;
        ob.z = (eb.z + rv * (z1f[6] + v0[6]) + dv * a[6]) * 0.25f;
        ob.w = (eb.w + rv * (z1f[7] + v0[7]) + dv * a[7]) * 0.25f;
        out4[o * 2] = oa;
        out4[o * 2 + 1] = ob;
    }
}

// ---------------------------------------------------------------------------
extern "C" void kernel_launch(void* const* d_in, const int* in_sizes, int n_in,
                              void* d_out, int out_size) {
    // Bind inputs by unique element count (robust to metadata ordering).
    const float* emb = nullptr;   // 6,400,000 f32
    const float* ew = nullptr;    // 1,600,000 f32
    const void* idx = nullptr;    // 3,200,000 elems (int32 or int64, detected)
    for (int i = 0; i < n_in; i++) {
        if (in_sizes[i] == ND) emb = (const float*)d_in[i];
        else if (in_sizes[i] == EE) ew = (const float*)d_in[i];
        else if (in_sizes[i] == 2 * EE) idx = d_in[i];
    }
    if (!emb) emb = (const float*)d_in[0];
    if (!ew) ew = (const float*)d_in[1];
    if (!idx) idx = d_in[2];

    float4* out4 = (float4*)d_out;

    uint4* z0;
    uint4* z1;
    uint4* z2;
    cudaGetSymbolAddress((void**)&z0, g_z0);
    cudaGetSymbolAddress((void**)&z1, g_z1);
    cudaGetSymbolAddress((void**)&z2, g_z2);

    const int T = 256;
    const int gN = (NN + T - 1) / T;            // 391
    const int gC = (ND8 + T - 1) / T;           // 3125
    const int gE4 = (EE / 4 + T - 1) / T;       // 1563
    const int gL = NN / 32;                     // 3125 (32 nodes/block)

    // Precompute: init, degrees+ranks, scan(+dinv,rdinv), fill+z0 (4 launches)
    k_init<<<gN, T>>>(idx);
    k_count<<<gE4, T>>>(idx);
    k_scan<<<NB, T>>>();
    k_fillz<<<gC, T>>>(idx, ew, (const float4*)emb);

    // Layer 1: z1 <- dinv^2 (z0 + A_w z0)
    k_layer<<<gL, T>>>(z0, z1, nullptr, nullptr, nullptr, 0);
    // Layer 2: z2
    k_layer<<<gL, T>>>(z1, z2, nullptr, nullptr, nullptr, 1);
    // Layer 3: out = (x0 + x1 + x2 + x3) / 4  (fp32 out)
    k_layer<<<gL, T>>>(z2, nullptr, (const float4*)emb, z1, out4, 2);
}